// round 10
// baseline (speedup 1.0000x reference)
#include <cuda_runtime.h>
#include <cuda_bf16.h>
#include <cstdint>

// GCN layer: out = segment_sum(val * x[col]) @ W^T + b
//  = b + segment_sum(val * (x @ W^T)[col])    (projection commutes with sum)
//
// K1: xW = x @ W^T via mma.sync tf32  +  fused rowptr boundary pass (overlaps
//     the 3.2MB edge_row read with tensor compute).
// K2: SpMM: 2 warps per node (64 dims each, float2/lane), 4-edge batches with
//     metadata (ecol/eval) software-pipelined one batch ahead.

#define D 128
#define MAX_N 50000
#define SPAD 132            // 128 + 4 padding words -> conflict-free frag loads

__device__ float g_xW[MAX_N * D];
__device__ int   g_rowptr[MAX_N + 1];

__device__ __forceinline__ float to_tf32(float f) {
    float r;
    asm("cvt.rna.tf32.f32 %0, %1;" : "=f"(r) : "f"(f));
    return r;
}

__device__ __forceinline__ void mma_tf32(float* d, const uint32_t* a, const uint32_t* b) {
    asm volatile(
        "mma.sync.aligned.m16n8k8.row.col.f32.tf32.tf32.f32 "
        "{%0,%1,%2,%3}, {%4,%5,%6,%7}, {%8,%9}, {%0,%1,%2,%3};"
        : "+f"(d[0]), "+f"(d[1]), "+f"(d[2]), "+f"(d[3])
        : "r"(a[0]), "r"(a[1]), "r"(a[2]), "r"(a[3]), "r"(b[0]), "r"(b[1]));
}

// ---------------------------------------------------------------------------
// K1: xW[i, o] = sum_k x[i,k] * W[o,k]   (+ fused rowptr build)
// 128x128 tile per CTA, 256 threads = 8 warps (4x2), warp tile 32x64.
// ---------------------------------------------------------------------------
__global__ __launch_bounds__(256, 1)
void gemm_xw_mma(const float* __restrict__ x, const float* __restrict__ W,
                 const int* __restrict__ erow, int N, int E) {
    extern __shared__ float smem[];
    float* As = smem;                 // [128][SPAD]
    float* Ws = smem + 128 * SPAD;    // [128][SPAD]

    const int tid = threadIdx.x;
    const int block_row = blockIdx.x * 128;

    // ---- fused rowptr: thread t handles edges [t*8, t*8+8), strided ----
    {
        const int nthreads = gridDim.x * blockDim.x;
        for (int base = (blockIdx.x * blockDim.x + tid) * 8; base < E;
             base += nthreads * 8) {
            int prev = (base == 0) ? -1 : __ldg(erow + base - 1);
            if (base + 8 <= E) {
                const int4 ca = __ldg(reinterpret_cast<const int4*>(erow + base));
                const int4 cb = __ldg(reinterpret_cast<const int4*>(erow + base + 4));
                const int rc[8] = {ca.x, ca.y, ca.z, ca.w, cb.x, cb.y, cb.z, cb.w};
                #pragma unroll
                for (int j = 0; j < 8; j++) {
                    const int cur = rc[j];
                    for (int r = prev; r < cur; r++) g_rowptr[r + 1] = base + j;
                    prev = cur;
                }
                if (base + 8 == E)
                    for (int r = prev; r < N; r++) g_rowptr[r + 1] = E;
            } else {
                for (int j = 0; j < E - base; j++) {
                    const int cur = __ldg(erow + base + j);
                    for (int r = prev; r < cur; r++) g_rowptr[r + 1] = base + j;
                    prev = cur;
                }
                for (int r = prev; r < N; r++) g_rowptr[r + 1] = E;
            }
            if (base == 0) g_rowptr[0] = 0;
        }
    }

    // ---- GEMM ----
    #pragma unroll
    for (int it = 0; it < 16; it++) {
        const int slot = tid + it * 256;        // float4 slot, 4096 total
        const int r = slot >> 5;
        const int c = (slot & 31) * 4;
        const int gr = block_row + r;
        float4 v = make_float4(0.f, 0.f, 0.f, 0.f);
        if (gr < N) v = *reinterpret_cast<const float4*>(x + (size_t)gr * D + c);
        float* dst = As + r * SPAD + c;
        dst[0] = to_tf32(v.x); dst[1] = to_tf32(v.y);
        dst[2] = to_tf32(v.z); dst[3] = to_tf32(v.w);
    }
    #pragma unroll
    for (int it = 0; it < 16; it++) {
        const int slot = tid + it * 256;
        const int r = slot >> 5;
        const int c = (slot & 31) * 4;
        float4 v = *reinterpret_cast<const float4*>(W + (size_t)r * D + c);
        float* dst = Ws + r * SPAD + c;
        dst[0] = to_tf32(v.x); dst[1] = to_tf32(v.y);
        dst[2] = to_tf32(v.z); dst[3] = to_tf32(v.w);
    }
    __syncthreads();

    const uint32_t* Ab = reinterpret_cast<const uint32_t*>(As);
    const uint32_t* Wb = reinterpret_cast<const uint32_t*>(Ws);

    const int wid  = tid >> 5;
    const int lane = tid & 31;
    const int grp  = lane >> 2;       // 0..7
    const int tig  = lane & 3;        // 0..3
    const int warpRow = (wid & 3) * 32;
    const int warpCol = (wid >> 2) * 64;

    float acc[2][8][4];
    #pragma unroll
    for (int mt = 0; mt < 2; mt++)
        #pragma unroll
        for (int nt = 0; nt < 8; nt++)
            #pragma unroll
            for (int q = 0; q < 4; q++) acc[mt][nt][q] = 0.f;

    #pragma unroll
    for (int ks = 0; ks < 16; ks++) {
        const int k0 = ks * 8;
        uint32_t a[2][4];
        #pragma unroll
        for (int mt = 0; mt < 2; mt++) {
            const int r0 = warpRow + mt * 16 + grp;
            a[mt][0] = Ab[r0 * SPAD + k0 + tig];
            a[mt][1] = Ab[(r0 + 8) * SPAD + k0 + tig];
            a[mt][2] = Ab[r0 * SPAD + k0 + tig + 4];
            a[mt][3] = Ab[(r0 + 8) * SPAD + k0 + tig + 4];
        }
        uint32_t b[8][2];
        #pragma unroll
        for (int nt = 0; nt < 8; nt++) {
            const int n0 = warpCol + nt * 8 + grp;
            b[nt][0] = Wb[n0 * SPAD + k0 + tig];
            b[nt][1] = Wb[n0 * SPAD + k0 + tig + 4];
        }
        #pragma unroll
        for (int mt = 0; mt < 2; mt++)
            #pragma unroll
            for (int nt = 0; nt < 8; nt++)
                mma_tf32(acc[mt][nt], a[mt], b[nt]);
    }

    #pragma unroll
    for (int mt = 0; mt < 2; mt++) {
        const int r0 = block_row + warpRow + mt * 16 + grp;
        #pragma unroll
        for (int nt = 0; nt < 8; nt++) {
            const int c0 = warpCol + nt * 8 + tig * 2;
            if (r0 < N)
                *reinterpret_cast<float2*>(g_xW + (size_t)r0 * D + c0) =
                    make_float2(acc[mt][nt][0], acc[mt][nt][1]);
            if (r0 + 8 < N)
                *reinterpret_cast<float2*>(g_xW + (size_t)(r0 + 8) * D + c0) =
                    make_float2(acc[mt][nt][2], acc[mt][nt][3]);
        }
    }
}

// ---------------------------------------------------------------------------
// K2: out[i] = b + sum_{e in [rp[i], rp[i+1])} val[e] * xW[col[e]]
// 2 warps per node. Metadata software-pipelined one 4-edge batch ahead.
// ---------------------------------------------------------------------------
#define FMA2(ACC, V, A) \
    do { ACC.x = fmaf(V, A.x, ACC.x); ACC.y = fmaf(V, A.y, ACC.y); } while (0)

__global__ __launch_bounds__(256)
void spmm_kernel(const int* __restrict__ ecol, const float* __restrict__ eval,
                 const float* __restrict__ b, float* __restrict__ out, int N) {
    const int gwarp = (blockIdx.x * blockDim.x + threadIdx.x) >> 5;
    const int node  = gwarp >> 1;
    const int half  = gwarp & 1;
    const int lane  = threadIdx.x & 31;
    if (node >= N) return;

    const int start = g_rowptr[node];
    const int end   = g_rowptr[node + 1];

    const int dim = half * 64 + lane * 2;
    const float* xw = g_xW + dim;

    float2 acc0 = *reinterpret_cast<const float2*>(b + dim);
    float2 acc1 = make_float2(0.f, 0.f);

    int e = start;
    while (e < end && (e & 3)) {           // peel to 4-alignment
        float2 a = *reinterpret_cast<const float2*>(xw + __ldg(ecol + e) * D);
        FMA2(acc0, __ldg(eval + e), a);
        e++;
    }

    int nb = (end - e) >> 2;               // full 4-edge batches
    if (nb > 0) {
        int4   c = __ldg(reinterpret_cast<const int4*>(ecol + e));
        float4 v = __ldg(reinterpret_cast<const float4*>(eval + e));
        while (--nb > 0) {
            const int4   cn = __ldg(reinterpret_cast<const int4*>(ecol + e + 4));
            const float4 vn = __ldg(reinterpret_cast<const float4*>(eval + e + 4));
            const float2 a0 = *reinterpret_cast<const float2*>(xw + c.x * D);
            const float2 a1 = *reinterpret_cast<const float2*>(xw + c.y * D);
            const float2 a2 = *reinterpret_cast<const float2*>(xw + c.z * D);
            const float2 a3 = *reinterpret_cast<const float2*>(xw + c.w * D);
            FMA2(acc0, v.x, a0); FMA2(acc1, v.y, a1);
            FMA2(acc0, v.z, a2); FMA2(acc1, v.w, a3);
            c = cn; v = vn; e += 4;
        }
        const float2 a0 = *reinterpret_cast<const float2*>(xw + c.x * D);
        const float2 a1 = *reinterpret_cast<const float2*>(xw + c.y * D);
        const float2 a2 = *reinterpret_cast<const float2*>(xw + c.z * D);
        const float2 a3 = *reinterpret_cast<const float2*>(xw + c.w * D);
        FMA2(acc0, v.x, a0); FMA2(acc1, v.y, a1);
        FMA2(acc0, v.z, a2); FMA2(acc1, v.w, a3);
        e += 4;
    }

    while (e < end) {                      // tail
        float2 a = *reinterpret_cast<const float2*>(xw + __ldg(ecol + e) * D);
        FMA2(acc0, __ldg(eval + e), a);
        e++;
    }

    acc0.x += acc1.x; acc0.y += acc1.y;
    *reinterpret_cast<float2*>(out + (size_t)node * D + dim) = acc0;
}

// ---------------------------------------------------------------------------
extern "C" void kernel_launch(void* const* d_in, const int* in_sizes, int n_in,
                              void* d_out, int out_size) {
    const float* x    = (const float*)d_in[0];
    const int*   erow = (const int*)  d_in[1];
    const int*   ecol = (const int*)  d_in[2];
    const float* eval = (const float*)d_in[3];
    const float* W    = (const float*)d_in[4];
    const float* b    = (const float*)d_in[5];

    const int N = in_sizes[0] / D;
    const int E = in_sizes[1];

    const int smem_bytes = 2 * 128 * SPAD * sizeof(float);   // ~135 KB
    cudaFuncSetAttribute(gemm_xw_mma, cudaFuncAttributeMaxDynamicSharedMemorySize, smem_bytes);

    gemm_xw_mma<<<(N + 127) / 128, 256, smem_bytes>>>(x, W, erow, N, E);

    const int total_warps = 2 * N;                 // 2 warps per node
    spmm_kernel<<<(total_warps * 32 + 255) / 256, 256>>>(ecol, eval, b, (float*)d_out, N);
}

// round 11
// speedup vs baseline: 1.1727x; 1.1727x over previous
#include <cuda_runtime.h>
#include <cuda_fp16.h>
#include <cstdint>

// GCN layer: out = segment_sum(val * x[col]) @ W^T + b
//  = b + segment_sum(val * (x @ W^T)[col])    (projection commutes with sum)
//
// K1: rowptr via one-pass boundary detection over sorted edge_row.
// K2: xW = x @ W^T via mma.sync tf32 (fp32 accum), epilogue stores fp16.
// K3: SpMM: 2 warps per node, lane owns 2 dims (half2 gather = one 128B line),
//     4-edge batches, fp32 accumulation. Halved L2 traffic vs fp32 xW.

#define D 128
#define MAX_N 50000
#define SPAD 132            // 128 + 4 padding words -> conflict-free frag loads

__device__ __half g_xWh[MAX_N * D];
__device__ int    g_rowptr[MAX_N + 1];

__device__ __forceinline__ float to_tf32(float f) {
    float r;
    asm("cvt.rna.tf32.f32 %0, %1;" : "=f"(r) : "f"(f));
    return r;
}

__device__ __forceinline__ void mma_tf32(float* d, const uint32_t* a, const uint32_t* b) {
    asm volatile(
        "mma.sync.aligned.m16n8k8.row.col.f32.tf32.tf32.f32 "
        "{%0,%1,%2,%3}, {%4,%5,%6,%7}, {%8,%9}, {%0,%1,%2,%3};"
        : "+f"(d[0]), "+f"(d[1]), "+f"(d[2]), "+f"(d[3])
        : "r"(a[0]), "r"(a[1]), "r"(a[2]), "r"(a[3]), "r"(b[0]), "r"(b[1]));
}

// ---------------------------------------------------------------------------
// K1: CSR offsets from sorted edge_row, one coalesced pass.
// ---------------------------------------------------------------------------
__global__ void rowptr_from_sorted(const int* __restrict__ rows, int E, int N) {
    const int e = blockIdx.x * blockDim.x + threadIdx.x;
    if (e >= E) return;
    const int cur  = __ldg(rows + e);
    const int prev = (e == 0) ? -1 : __ldg(rows + e - 1);
    for (int r = prev; r < cur; r++) g_rowptr[r + 1] = e;
    if (e == 0) g_rowptr[0] = 0;
    if (e == E - 1)
        for (int r = cur; r < N; r++) g_rowptr[r + 1] = E;
}

// ---------------------------------------------------------------------------
// K2: xW[i, o] = sum_k x[i,k] * W[o,k], stored as fp16.
// 128x128 tile per CTA, 256 threads = 8 warps (4x2), warp tile 32x64.
// ---------------------------------------------------------------------------
__global__ __launch_bounds__(256, 1)
void gemm_xw_mma(const float* __restrict__ x, const float* __restrict__ W, int N) {
    extern __shared__ float smem[];
    float* As = smem;                 // [128][SPAD]
    float* Ws = smem + 128 * SPAD;    // [128][SPAD]

    const int tid = threadIdx.x;
    const int block_row = blockIdx.x * 128;

    #pragma unroll
    for (int it = 0; it < 16; it++) {
        const int slot = tid + it * 256;        // float4 slot, 4096 total
        const int r = slot >> 5;
        const int c = (slot & 31) * 4;
        const int gr = block_row + r;
        float4 v = make_float4(0.f, 0.f, 0.f, 0.f);
        if (gr < N) v = *reinterpret_cast<const float4*>(x + (size_t)gr * D + c);
        float* dst = As + r * SPAD + c;
        dst[0] = to_tf32(v.x); dst[1] = to_tf32(v.y);
        dst[2] = to_tf32(v.z); dst[3] = to_tf32(v.w);
    }
    #pragma unroll
    for (int it = 0; it < 16; it++) {
        const int slot = tid + it * 256;
        const int r = slot >> 5;
        const int c = (slot & 31) * 4;
        float4 v = *reinterpret_cast<const float4*>(W + (size_t)r * D + c);
        float* dst = Ws + r * SPAD + c;
        dst[0] = to_tf32(v.x); dst[1] = to_tf32(v.y);
        dst[2] = to_tf32(v.z); dst[3] = to_tf32(v.w);
    }
    __syncthreads();

    const uint32_t* Ab = reinterpret_cast<const uint32_t*>(As);
    const uint32_t* Wb = reinterpret_cast<const uint32_t*>(Ws);

    const int wid  = tid >> 5;
    const int lane = tid & 31;
    const int grp  = lane >> 2;       // 0..7
    const int tig  = lane & 3;        // 0..3
    const int warpRow = (wid & 3) * 32;
    const int warpCol = (wid >> 2) * 64;

    float acc[2][8][4];
    #pragma unroll
    for (int mt = 0; mt < 2; mt++)
        #pragma unroll
        for (int nt = 0; nt < 8; nt++)
            #pragma unroll
            for (int q = 0; q < 4; q++) acc[mt][nt][q] = 0.f;

    #pragma unroll
    for (int ks = 0; ks < 16; ks++) {
        const int k0 = ks * 8;
        uint32_t a[2][4];
        #pragma unroll
        for (int mt = 0; mt < 2; mt++) {
            const int r0 = warpRow + mt * 16 + grp;
            a[mt][0] = Ab[r0 * SPAD + k0 + tig];
            a[mt][1] = Ab[(r0 + 8) * SPAD + k0 + tig];
            a[mt][2] = Ab[r0 * SPAD + k0 + tig + 4];
            a[mt][3] = Ab[(r0 + 8) * SPAD + k0 + tig + 4];
        }
        uint32_t b[8][2];
        #pragma unroll
        for (int nt = 0; nt < 8; nt++) {
            const int n0 = warpCol + nt * 8 + grp;
            b[nt][0] = Wb[n0 * SPAD + k0 + tig];
            b[nt][1] = Wb[n0 * SPAD + k0 + tig + 4];
        }
        #pragma unroll
        for (int mt = 0; mt < 2; mt++)
            #pragma unroll
            for (int nt = 0; nt < 8; nt++)
                mma_tf32(acc[mt][nt], a[mt], b[nt]);
    }

    // Epilogue: write fp16. c0/c1 -> (row, 2*tig), c2/c3 -> (row+8, 2*tig)
    #pragma unroll
    for (int mt = 0; mt < 2; mt++) {
        const int r0 = block_row + warpRow + mt * 16 + grp;
        #pragma unroll
        for (int nt = 0; nt < 8; nt++) {
            const int c0 = warpCol + nt * 8 + tig * 2;
            if (r0 < N)
                *reinterpret_cast<__half2*>(g_xWh + (size_t)r0 * D + c0) =
                    __floats2half2_rn(acc[mt][nt][0], acc[mt][nt][1]);
            if (r0 + 8 < N)
                *reinterpret_cast<__half2*>(g_xWh + (size_t)(r0 + 8) * D + c0) =
                    __floats2half2_rn(acc[mt][nt][2], acc[mt][nt][3]);
        }
    }
}

// ---------------------------------------------------------------------------
// K3: out[i] = b + sum_{e in [rp[i], rp[i+1])} val[e] * xW[col[e]]
// 2 warps per node: warp half h owns dims [h*64, h*64+64), half2 per lane.
// ---------------------------------------------------------------------------
#define FMA2(ACC, V, A) \
    do { ACC.x = fmaf(V, A.x, ACC.x); ACC.y = fmaf(V, A.y, ACC.y); } while (0)

__global__ __launch_bounds__(256)
void spmm_kernel(const int* __restrict__ ecol, const float* __restrict__ eval,
                 const float* __restrict__ b, float* __restrict__ out, int N) {
    const int gwarp = (blockIdx.x * blockDim.x + threadIdx.x) >> 5;
    const int node  = gwarp >> 1;
    const int half  = gwarp & 1;
    const int lane  = threadIdx.x & 31;
    if (node >= N) return;

    const int start = g_rowptr[node];
    const int end   = g_rowptr[node + 1];

    const int dim = half * 64 + lane * 2;
    const __half* xw = g_xWh + dim;

    float2 acc0 = *reinterpret_cast<const float2*>(b + dim);
    float2 acc1 = make_float2(0.f, 0.f);

    int e = start;
    while (e < end && (e & 3)) {           // peel to 4-alignment
        float2 a = __half22float2(
            *reinterpret_cast<const __half2*>(xw + (size_t)__ldg(ecol + e) * D));
        FMA2(acc0, __ldg(eval + e), a);
        e++;
    }
    for (; e + 4 <= end; e += 4) {         // main: 4 edges, 4 one-line gathers
        const int4   c = __ldg(reinterpret_cast<const int4*>(ecol + e));
        const float4 v = __ldg(reinterpret_cast<const float4*>(eval + e));
        const __half2 h0 = *reinterpret_cast<const __half2*>(xw + (size_t)c.x * D);
        const __half2 h1 = *reinterpret_cast<const __half2*>(xw + (size_t)c.y * D);
        const __half2 h2 = *reinterpret_cast<const __half2*>(xw + (size_t)c.z * D);
        const __half2 h3 = *reinterpret_cast<const __half2*>(xw + (size_t)c.w * D);
        const float2 a0 = __half22float2(h0);
        const float2 a1 = __half22float2(h1);
        const float2 a2 = __half22float2(h2);
        const float2 a3 = __half22float2(h3);
        FMA2(acc0, v.x, a0); FMA2(acc1, v.y, a1);
        FMA2(acc0, v.z, a2); FMA2(acc1, v.w, a3);
    }
    while (e < end) {                      // tail
        float2 a = __half22float2(
            *reinterpret_cast<const __half2*>(xw + (size_t)__ldg(ecol + e) * D));
        FMA2(acc0, __ldg(eval + e), a);
        e++;
    }

    acc0.x += acc1.x; acc0.y += acc1.y;
    *reinterpret_cast<float2*>(out + (size_t)node * D + dim) = acc0;
}

// ---------------------------------------------------------------------------
extern "C" void kernel_launch(void* const* d_in, const int* in_sizes, int n_in,
                              void* d_out, int out_size) {
    const float* x    = (const float*)d_in[0];
    const int*   erow = (const int*)  d_in[1];
    const int*   ecol = (const int*)  d_in[2];
    const float* eval = (const float*)d_in[3];
    const float* W    = (const float*)d_in[4];
    const float* b    = (const float*)d_in[5];

    const int N = in_sizes[0] / D;
    const int E = in_sizes[1];

    const int smem_bytes = 2 * 128 * SPAD * sizeof(float);   // ~135 KB
    cudaFuncSetAttribute(gemm_xw_mma, cudaFuncAttributeMaxDynamicSharedMemorySize, smem_bytes);

    rowptr_from_sorted<<<(E + 255) / 256, 256>>>(erow, E, N);
    gemm_xw_mma<<<(N + 127) / 128, 256, smem_bytes>>>(x, W, N);

    const int total_warps = 2 * N;                 // 2 warps per node
    spmm_kernel<<<(total_warps * 32 + 255) / 256, 256>>>(ecol, eval, b, (float*)d_out, N);
}